// round 12
// baseline (speedup 1.0000x reference)
#include <cuda_runtime.h>
#include <cuda_fp16.h>

#define NN      131072
#define KK      27
#define C       32
#define NCOL    (KK * C)           // 864 contrib columns
#define NKTOT   (NN * KK)
#define HCAP    48                 // per-(node, half) capacity (Poisson(13.5), P(>48)~e^-26)
#define EPS_F   1e-5f
#define GEMM_BLKS 1024             // NN/128
#define FILL_BLKS (NKTOT / 4 / 256)
#define GB2     (NN / 8)           // pass-2 gather blocks = BN partial count (16384)
#define MIDB    256

// -------- device scratch --------
__device__ __align__(16) __half g_contrib16[(size_t)NKTOT * C];      // 226 MB
__device__ int    g_fill2[NN * 2];
__device__ __align__(16) int g_list[(size_t)NN * 2 * HCAP];          // 50 MB split buckets
__device__ float  g_part[GB2 * 64];
__device__ float  g_part2[MIDB * 64];
__device__ float  g_stats[64];
__device__ __align__(16) unsigned g_bfrag[108 * 2 * 32 * 2];         // 55 KB: B frag order

__device__ __forceinline__ unsigned smem_u32(const void* p) {
    unsigned a;
    asm("{ .reg .u64 t; cvta.to.shared.u64 t, %1; cvt.u32.u64 %0, t; }" : "=r"(a) : "l"(p));
    return a;
}

// -------- 1. init: zero split counters + pre-swizzle B into mma frag order --
// Bfrag[nt][s][lane][reg]: k0 = s*16 + (l&3)*2 + reg*8, n = nt*8 + (l>>2),
// value half2( B[k0][n], B[k0+1][n] ), B[i][j] = weight[j/32][i][j%32].
__global__ void k_init(const float* __restrict__ weight) {
    int i = blockIdx.x * blockDim.x + threadIdx.x;       // grid covers 2*NN
    if (i < NN * 2) g_fill2[i] = 0;
    if (i < 108 * 2 * 32 * 2) {
        int reg = i & 1, l = (i >> 1) & 31, s = (i >> 6) & 1, nt = i >> 7;
        int k0 = s * 16 + (l & 3) * 2 + reg * 8;
        int n  = nt * 8 + (l >> 2);
        int jk = n >> 5, o = n & 31;
        float lo = weight[(jk * 32 + k0) * 32 + o];
        float hi = weight[(jk * 32 + k0 + 1) * 32 + o];
        __half2 h = __floats2half2_rn(lo, hi);
        g_bfrag[i] = *reinterpret_cast<unsigned*>(&h);
    }
}

// -------- 2. merged work kernel: GEMM (blocks 0..1023) + fill (rest) --------
// GEMM verbatim from R4 (column perm p = j*8 + t*2 + b <-> o = t*8 + j*2 + b),
// stores evict-normal so the high-n tail stays L2-resident for gather pass 1.
// Fill appends entry e = n*27+k to bucket (m, h) with h = (n >= NN/2).
__global__ __launch_bounds__(256) void k_work(const float* __restrict__ data,
                                              const int* __restrict__ neigh) {
    __shared__ __align__(16) __half Ah[128][40];
    const int tid = threadIdx.x, lane = tid & 31, warp = tid >> 5;

    if (blockIdx.x >= GEMM_BLKS) {
        int t = (blockIdx.x - GEMM_BLKS) * 256 + tid;
        int4 m4 = __ldcs(reinterpret_cast<const int4*>(neigh) + t);
        int e0 = t * 4;
#pragma unroll
        for (int q = 0; q < 4; ++q) {
            int m = (q == 0) ? m4.x : (q == 1) ? m4.y : (q == 2) ? m4.z : m4.w;
            int e = e0 + q;
            int n = (int)((unsigned)e / 27u);
            int h = (n >= NN / 2);
            int pos = atomicAdd(&g_fill2[m * 2 + h], 1);
            if (pos < HCAP)
                __stcs(&g_list[((size_t)m * 2 + h) * HCAP + pos], e);
        }
        return;
    }

    // ---- GEMM ----
    const int bid = blockIdx.x;
    const float4* src = reinterpret_cast<const float4*>(data + (size_t)bid * 128 * C);
#pragma unroll
    for (int t0 = 0; t0 < 4; ++t0) {
        int    t = tid + t0 * 256;
        float4 v = src[t];
        int r = t >> 3, c = (t & 7) * 4;
        *reinterpret_cast<__half2*>(&Ah[r][c])     = __floats2half2_rn(v.x, v.y);
        *reinterpret_cast<__half2*>(&Ah[r][c + 2]) = __floats2half2_rn(v.z, v.w);
    }
    __syncthreads();

    unsigned a0[4], a1[4];
    {
        unsigned base = smem_u32(&Ah[warp * 16 + (lane & 15)][(lane >> 4) * 8]);
        asm volatile("ldmatrix.sync.aligned.m8n8.x4.shared.b16 {%0,%1,%2,%3}, [%4];"
                     : "=r"(a0[0]), "=r"(a0[1]), "=r"(a0[2]), "=r"(a0[3]) : "r"(base));
        asm volatile("ldmatrix.sync.aligned.m8n8.x4.shared.b16 {%0,%1,%2,%3}, [%4];"
                     : "=r"(a1[0]), "=r"(a1[1]), "=r"(a1[2]), "=r"(a1[3]) : "r"(base + 32));
    }

    const int r0 = lane >> 2;
    const int j  = lane & 3;
    const size_t nlo = (size_t)bid * 128 + warp * 16 + r0;
    __half* plo = g_contrib16 + nlo * NCOL + j * 8;
    __half* phi = plo + (size_t)8 * NCOL;
    const uint2* bf = reinterpret_cast<const uint2*>(g_bfrag) + lane;

    for (int kb = 0; kb < 27; ++kb) {
        uint2 b[8];
#pragma unroll
        for (int q = 0; q < 8; ++q) b[q] = bf[(kb * 8 + q) * 32];

        unsigned hlo[4], hhi[4];
#pragma unroll
        for (int t = 0; t < 4; ++t) {
            float d0 = 0.f, d1 = 0.f, d2 = 0.f, d3 = 0.f;
            asm volatile(
                "mma.sync.aligned.m16n8k16.row.col.f32.f16.f16.f32 "
                "{%0,%1,%2,%3}, {%4,%5,%6,%7}, {%8,%9}, {%0,%1,%2,%3};"
                : "+f"(d0), "+f"(d1), "+f"(d2), "+f"(d3)
                : "r"(a0[0]), "r"(a0[1]), "r"(a0[2]), "r"(a0[3]),
                  "r"(b[t * 2].x), "r"(b[t * 2].y));
            asm volatile(
                "mma.sync.aligned.m16n8k16.row.col.f32.f16.f16.f32 "
                "{%0,%1,%2,%3}, {%4,%5,%6,%7}, {%8,%9}, {%0,%1,%2,%3};"
                : "+f"(d0), "+f"(d1), "+f"(d2), "+f"(d3)
                : "r"(a1[0]), "r"(a1[1]), "r"(a1[2]), "r"(a1[3]),
                  "r"(b[t * 2 + 1].x), "r"(b[t * 2 + 1].y));
            __half2 l2 = __floats2half2_rn(d0, d1);
            __half2 h2 = __floats2half2_rn(d2, d3);
            hlo[t] = *reinterpret_cast<unsigned*>(&l2);
            hhi[t] = *reinterpret_cast<unsigned*>(&h2);
        }
        *reinterpret_cast<uint4*>(plo + kb * 32) = make_uint4(hlo[0], hlo[1], hlo[2], hlo[3]);
        *reinterpret_cast<uint4*>(phi + kb * 32) = make_uint4(hhi[0], hhi[1], hhi[2], hhi[3]);
    }
}

// -------- 3. gather pass (templated): sum bucket (m, H) of contrib ---------
// warp = node; lanes 0-15 entry A / 16-31 entry B of each pair, half2 per lane.
// Pass H=1 runs first (contrib high-n window, harvests GEMM's L2 tail) and
// writes raw sums; pass H=0 accumulates onto out and emits BN partials.
template <int H, bool FINAL>
__global__ __launch_bounds__(256) void k_gpass(float* __restrict__ out) {
    __shared__ float sm[8][33];
    const int tid = threadIdx.x, lane = tid & 31, w = tid >> 5;
    const int m = blockIdx.x * 8 + w;
    const int hsel = lane >> 4;
    const int ch2  = lane & 15;
    int cnt = g_fill2[m * 2 + H];
    if (cnt > HCAP) cnt = HCAP;
    const int* lst = g_list + ((size_t)m * 2 + H) * HCAP;

    float2 acc = make_float2(0.f, 0.f);
    int j = 0;
    for (; j + 16 <= cnt; j += 16) {
        __half2 v[8];
#pragma unroll
        for (int t = 0; t < 8; ++t) {
            int e = lst[j + 2 * t + hsel];
            v[t]  = *reinterpret_cast<const __half2*>(
                        g_contrib16 + (size_t)e * C + ch2 * 2);
        }
#pragma unroll
        for (int t = 0; t < 8; ++t) {
            float2 f = __half22float2(v[t]);
            acc.x += f.x; acc.y += f.y;
        }
    }
    for (; j + 2 <= cnt; j += 2) {
        int     e = lst[j + hsel];
        __half2 v = *reinterpret_cast<const __half2*>(
                        g_contrib16 + (size_t)e * C + ch2 * 2);
        float2  f = __half22float2(v);
        acc.x += f.x; acc.y += f.y;
    }
    if (j < cnt && hsel == 0) {
        int     e = lst[j];
        __half2 v = *reinterpret_cast<const __half2*>(
                        g_contrib16 + (size_t)e * C + ch2 * 2);
        float2  f = __half22float2(v);
        acc.x += f.x; acc.y += f.y;
    }
    acc.x += __shfl_down_sync(0xffffffffu, acc.x, 16);
    acc.y += __shfl_down_sync(0xffffffffu, acc.y, 16);

    if (hsel == 0) {
        // undo GEMM column permutation: half2 idx p2 -> channel (p2&3)*8+(p2>>2)*2
        int co = (ch2 & 3) * 8 + (ch2 >> 2) * 2;
        float2* po = reinterpret_cast<float2*>(out + (size_t)m * C + co);
        if (FINAL) {
            float2 prev = *po;
            acc.x += prev.x; acc.y += prev.y;
        }
        *po = acc;
        if (FINAL) { sm[w][co] = acc.x; sm[w][co + 1] = acc.y; }
    }
    if (FINAL) {
        __syncthreads();
        if (tid < 32) {                  // deterministic per-CTA BN partials
            float s = 0.f, q = 0.f;
#pragma unroll
            for (int r = 0; r < 8; ++r) {
                float v = sm[r][tid];
                s += v; q += v * v;
            }
            g_part[blockIdx.x * 64 + tid]      = s;
            g_part[blockIdx.x * 64 + 32 + tid] = q;
        }
    }
}

// -------- 4. BN partial reduction: 16384 -> 256 --------
__global__ __launch_bounds__(256) void k_bnmid() {
    __shared__ float ss[8][32], sq[8][32];
    int ch = threadIdx.x & 31, w = threadIdx.x >> 5;
    float s = 0.f, q = 0.f;
    for (int p = blockIdx.x * 64 + w; p < (blockIdx.x + 1) * 64; p += 8) {
        s += g_part[p * 64 + ch];
        q += g_part[p * 64 + 32 + ch];
    }
    ss[w][ch] = s; sq[w][ch] = q;
    __syncthreads();
    if (w == 0) {
        float S = 0.f, Q = 0.f;
#pragma unroll
        for (int t = 0; t < 8; ++t) { S += ss[t][ch]; Q += sq[t][ch]; }
        g_part2[blockIdx.x * 64 + ch]      = S;
        g_part2[blockIdx.x * 64 + 32 + ch] = Q;
    }
}

// -------- 5. BN finalize --------
__global__ __launch_bounds__(256) void k_bnfinal(const float* __restrict__ gamma,
                                                 const float* __restrict__ beta) {
    __shared__ float ss[8][32], sq[8][32];
    int ch = threadIdx.x & 31, w = threadIdx.x >> 5;
    float S = 0.f, Q = 0.f;
    for (int b = w; b < MIDB; b += 8) {
        S += g_part2[b * 64 + ch];
        Q += g_part2[b * 64 + 32 + ch];
    }
    ss[w][ch] = S; sq[w][ch] = Q;
    __syncthreads();
    if (w == 0) {
        float St = 0.f, Qt = 0.f;
#pragma unroll
        for (int t = 0; t < 8; ++t) { St += ss[t][ch]; Qt += sq[t][ch]; }
        float mean  = St * (1.0f / NN);
        float var   = Qt * (1.0f / NN) - mean * mean;
        float rstd  = rsqrtf(var + EPS_F);
        float scale = gamma[ch] * rstd;
        g_stats[ch]      = scale;
        g_stats[32 + ch] = beta[ch] - mean * scale;
    }
}

// -------- 6. apply BN + ReLU --------
__global__ __launch_bounds__(256) void k_apply(float* __restrict__ out) {
    int i = blockIdx.x * blockDim.x + threadIdx.x;
    if (i >= NN * C) return;
    int   ch = i & 31;
    float y  = fmaf(out[i], g_stats[ch], g_stats[32 + ch]);
    out[i] = fmaxf(y, 0.f);
}

extern "C" void kernel_launch(void* const* d_in, const int* in_sizes, int n_in,
                              void* d_out, int out_size) {
    const float* data   = (const float*)d_in[0];
    const float* weight = (const float*)d_in[1];
    const float* gamma  = (const float*)d_in[2];
    const float* beta   = (const float*)d_in[3];
    const int*   neigh  = (const int*)d_in[4];
    float*       out    = (float*)d_out;

    k_init<<<NN * 2 / 256, 256>>>(weight);
    k_work<<<GEMM_BLKS + FILL_BLKS, 256>>>(data, neigh);
    k_gpass<1, false><<<GB2, 256>>>(out);   // high-n window first (L2 tail)
    k_gpass<0, true><<<GB2, 256>>>(out);    // low-n window + BN stage-1
    k_bnmid<<<MIDB, 256>>>();
    k_bnfinal<<<1, 256>>>(gamma, beta);
    k_apply<<<(NN * C + 255) / 256, 256>>>(out);
}